// round 17
// baseline (speedup 1.0000x reference)
#include <cuda_runtime.h>
#include <math_constants.h>
#include <cstdint>

// SubsetOperator soft k-hot (K=16, TAU=1), exp-domain, fixed shift (-10):
//   e = exp(s0-10); repeat K: p = e/Z; khot += p; e *= (1-p)
// R12 structure (512 thr, 2 CTAs/SM, 2-iter bodies, sign-flip renorm:
//   b=-p1*t => b*b+b = -(renormalized next state))
// Fold path: per-warp redux.sync.add.u32 of scaled (A,B), lane0 does ONE
// u64 atomicAdd of (A<<32 | B) -> half the ATOMS traffic; post-barrier is
// one LDS.64 + parallel scalar chain p0=rcp(A), p1=a*rcp(A*a-b).

#define ROWS 4096
#define NCOL 8192
#define THREADS 512
#define PAIRS 8
#define GRID 296

typedef unsigned long long u64;
typedef unsigned int u32;

#define MUL2(d,a,b)    asm("mul.rn.f32x2 %0, %1, %2;"     : "=l"(d) : "l"(a), "l"(b))
#define ADD2(d,a,b)    asm("add.rn.f32x2 %0, %1, %2;"     : "=l"(d) : "l"(a), "l"(b))
#define FMA2(d,a,b,c)  asm("fma.rn.f32x2 %0, %1, %2, %3;" : "=l"(d) : "l"(a), "l"(b), "l"(c))
#define PACK2(d,lo,hi)   asm("mov.b64 %0, {%1, %2};" : "=l"(d) : "f"(lo), "f"(hi))
#define UNPACK2(lo,hi,s) asm("mov.b64 {%0, %1}, %2;" : "=f"(lo), "=f"(hi) : "l"(s))

__device__ __forceinline__ float rcp_fast(float x) {
    float r; asm("rcp.approx.f32 %0, %1;" : "=f"(r) : "f"(x)); return r;
}
__device__ __forceinline__ float ex2_fast(float x) {
    float r; asm("ex2.approx.f32 %0, %1;" : "=f"(r) : "f"(x)); return r;
}
__device__ __forceinline__ u32 f2u_rni(float x) {
    u32 u; asm("cvt.rni.u32.f32 %0, %1;" : "=r"(u) : "f"(x)); return u;
}
__device__ __forceinline__ float u2f(u32 u) {
    float x; asm("cvt.rn.f32.u32 %0, %1;" : "=f"(x) : "r"(u)); return x;
}
__device__ __forceinline__ u32 redux_add_u32(u32 v) {
    u32 d; asm("redux.sync.add.u32 %0, %1, 0xffffffff;" : "=r"(d) : "r"(v)); return d;
}

#define SCALE_F  268435456.0f            // 2^28
#define NSCALE_F -268435456.0f
#define ISCALE_F 3.725290298461914e-9f   // 2^-28

__device__ __forceinline__ void cp16(u32 dst, const void* src) {
    asm volatile("cp.async.cg.shared.global [%0], [%1], 16;" :: "r"(dst), "l"(src));
}

__device__ __forceinline__ void prefetch_row(const float* s, const float* gg,
                                             int row, float* tile, int tid, bool valid) {
    if (valid) {
        const float4* s4 = (const float4*)(s + (size_t)row * NCOL);
        const float4* g4 = (const float4*)(gg + (size_t)row * NCOL);
        u32 ds = (u32)__cvta_generic_to_shared(tile);
#pragma unroll
        for (int c = 0; c < 4; c++) {
            cp16(ds + (u32)(tid + c * THREADS) * 16u,                  s4 + tid + c * THREADS);
            cp16(ds + (u32)NCOL * 4u + (u32)(tid + c * THREADS) * 16u, g4 + tid + c * THREADS);
        }
    }
    asm volatile("cp.async.commit_group;");
}

__global__ void __launch_bounds__(THREADS, 2)
subset_op_kernel(const float* __restrict__ scores,
                 const float* __restrict__ g,
                 float* __restrict__ out) {
    extern __shared__ __align__(16) float tile[];     // 64 KB
    __shared__ __align__(16) float2 redf[16];
    __shared__ __align__(16) u64 acc[7];              // packed (A<<32 | B) per body

    const int tid  = threadIdx.x;
    const int lane = tid & 31;
    const int wid  = tid >> 5;
    const float L2E = 1.4426950408889634f;
    const float CC  = -10.0f * L2E;

    int row = blockIdx.x;
    prefetch_row(scores, g, row, tile, tid, true);

    for (; row < ROWS; row += GRID) {
        asm volatile("cp.async.wait_group 0;");
        __syncthreads();
        if (tid < 7) acc[tid] = 0ull;

        // ---- prologue: exp; (A,B) f32 partials (Z0 unnormalized -> f32 path) ----
        u64 t[PAIRS], nk[PAIRS];
        const float4* ts4 = (const float4*)tile;
        const float4* tg4 = (const float4*)(tile + NCOL);
        u64 ma = 0ull, mb = 0ull;
#pragma unroll
        for (int c = 0; c < 4; c++) {
            const int i4 = tid + c * THREADS;
            float4 a = ts4[i4];
            float4 b = tg4[i4];
            float e0 = ex2_fast(fmaf(a.x + b.x, L2E, CC));
            float e1 = ex2_fast(fmaf(a.y + b.y, L2E, CC));
            float e2 = ex2_fast(fmaf(a.z + b.z, L2E, CC));
            float e3 = ex2_fast(fmaf(a.w + b.w, L2E, CC));
            PACK2(t[2 * c],     e0, e1);
            PACK2(t[2 * c + 1], e2, e3);
            nk[2 * c] = 0ull; nk[2 * c + 1] = 0ull;
            ADD2(ma, ma, t[2 * c]);
            ADD2(ma, ma, t[2 * c + 1]);
            FMA2(mb, t[2 * c],     t[2 * c],     mb);
            FMA2(mb, t[2 * c + 1], t[2 * c + 1], mb);
        }
        prefetch_row(scores, g, row + GRID, tile, tid, (row + GRID) < ROWS);

        float Af, Bf;
        {
            float lo, hi;
            UNPACK2(lo, hi, ma); Af = lo + hi;
            UNPACK2(lo, hi, mb); Bf = lo + hi;
            u64 u; PACK2(u, Af, Bf);
#pragma unroll
            for (int o = 16; o > 0; o >>= 1) {
                u64 x = __shfl_xor_sync(0xffffffffu, u, o);
                ADD2(u, u, x);
            }
            if (lane == 0) { float2 q; UNPACK2(q.x, q.y, u); redf[wid] = q; }
            __syncthreads();
            float2 v = redf[lane & 15];
            PACK2(u, v.x, v.y);
#pragma unroll
            for (int o = 8; o > 0; o >>= 1) {
                u64 x = __shfl_xor_sync(0xffffffffu, u, o);
                ADD2(u, u, x);
            }
            UNPACK2(Af, Bf, u);
        }

        // body-0 scalars from f32 (A,B)
        float p0 = rcp_fast(Af);
        float p1 = Af * rcp_fast(fmaf(Af, Af, -Bf));   // 1/(A - B/A)

        // ---- bodies 0..6: 2 iters + fold; state negated after each body ----
#pragma unroll
        for (int r = 0; r < 7; r++) {
            const float sg = (r == 0) ? -1.0f : 1.0f;
            u64 vv, ww;
            PACK2(vv, sg * p0, sg * p0);
            PACK2(ww, sg * p1, sg * p1);

            // iterA: q = -p0*t_true ; nk += q ; t *= (1+q)
#pragma unroll
            for (int j = 0; j < PAIRS; j++) {
                u64 q;
                MUL2(q, t[j], vv);
                ADD2(nk[j], nk[j], q);
                FMA2(t[j], q, t[j], t[j]);
            }
            // iterB: b = -p1*t_true ; nk += b ; t = b*b + b ; fold (A,B)
            u64 fa = 0ull, fb = 0ull;
#pragma unroll
            for (int j = 0; j < PAIRS; j++) {
                u64 b;
                MUL2(b, t[j], ww);
                ADD2(nk[j], nk[j], b);
                FMA2(t[j], b, b, b);          // -(renormalized next state)
                ADD2(fa, fa, t[j]);
                FMA2(fb, t[j], t[j], fb);
            }
            // fold: scale+cvt, warp redux, ONE u64 atomic per warp
            {
                float lo, hi, pa, pb;
                UNPACK2(lo, hi, fa); pa = lo + hi;   // negative (state negated)
                UNPACK2(lo, hi, fb); pb = lo + hi;
                u32 ua = redux_add_u32(f2u_rni(pa * NSCALE_F));
                u32 ub = redux_add_u32(f2u_rni(pb * SCALE_F));
                if (lane == 0)
                    atomicAdd(&acc[r], ((u64)ua << 32) | (u64)ub);
            }
            __syncthreads();
            // scalars for next body: a,b fixed-point; p0 = rcp(a*IS),
            // p1 = a * rcp((a*IS)*a - b)  [= 1/(A - B/A), parallel chains]
            {
                u64 v = acc[r];
                float a = u2f((u32)(v >> 32));
                float b = u2f((u32)v);
                float A = a * ISCALE_F;
                p0 = rcp_fast(A);
                p1 = a * rcp_fast(fmaf(A, a, -b));
            }
        }

        // ---- body 7: iterA + final iteration (state negated => sg=+1) ----
        {
            u64 vv, ww;
            PACK2(vv, p0, p0);
            PACK2(ww, p1, p1);
#pragma unroll
            for (int j = 0; j < PAIRS; j++) {
                u64 q;
                MUL2(q, t[j], vv);
                ADD2(nk[j], nk[j], q);
                FMA2(t[j], q, t[j], t[j]);
            }
#pragma unroll
            for (int j = 0; j < PAIRS; j++) {
                u64 q;
                MUL2(q, t[j], ww);
                ADD2(nk[j], nk[j], q);
            }
        }

        // ---- store khot = -nk ----
        float4* o4 = (float4*)(out + (size_t)row * NCOL);
#pragma unroll
        for (int c = 0; c < 4; c++) {
            float a0, a1, a2, a3;
            UNPACK2(a0, a1, nk[2 * c]);
            UNPACK2(a2, a3, nk[2 * c + 1]);
            float4 v; v.x = -a0; v.y = -a1; v.z = -a2; v.w = -a3;
            o4[tid + c * THREADS] = v;
        }
        __syncthreads();   // protect redf/acc reuse next row
    }
}

extern "C" void kernel_launch(void* const* d_in, const int* in_sizes, int n_in,
                              void* d_out, int out_size) {
    const float* scores = (const float*)d_in[0];
    const float* g      = (const float*)d_in[1];
    float* out          = (float*)d_out;
    cudaFuncSetAttribute(subset_op_kernel,
                         cudaFuncAttributeMaxDynamicSharedMemorySize, 2 * NCOL * 4);
    subset_op_kernel<<<GRID, THREADS, 2 * NCOL * 4>>>(scores, g, out);
}